// round 3
// baseline (speedup 1.0000x reference)
#include <cuda_runtime.h>

#define BATCH 8
#define SEQ   2500
#define DIM   128
#define NCLS  8921
#define CT    128
#define LT    128
#define NCHUNK 20
#define THREADS 256
#define ROWW  128   // floats per smem row (no pad; swizzle instead)

#define SMEM_BYTES (3 * 128 * 128 * 4)   // Us, xL, P : 196608 B

typedef unsigned long long u64;

// float offset of 4-float group g within row: additive swizzle, conflict-free
__device__ __forceinline__ int swoff(int row, int g) {
    return row * ROWW + (((g + (row >> 2)) & 31) << 2);
}

__device__ __forceinline__ u64 pack2(float lo, float hi) {
    u64 r; asm("mov.b64 %0, {%1, %2};" : "=l"(r) : "f"(lo), "f"(hi)); return r;
}
__device__ __forceinline__ u64 rep2(float v) {
    u64 r; asm("mov.b64 %0, {%1, %1};" : "=l"(r) : "f"(v)); return r;
}
__device__ __forceinline__ void unpack2(u64 v, float& lo, float& hi) {
    asm("mov.b64 {%0, %1}, %2;" : "=f"(lo), "=f"(hi) : "l"(v));
}
__device__ __forceinline__ void fma2(u64& d, u64 a, u64 b) {
    asm("fma.rn.f32x2 %0, %1, %2, %0;" : "+l"(d) : "l"(a), "l"(b));
}
__device__ __forceinline__ void mul2(u64& d, u64 a) {
    asm("mul.rn.f32x2 %0, %0, %1;" : "+l"(d) : "l"(a));
}

__global__ __launch_bounds__(THREADS, 1)
void lwa_kernel(const float* __restrict__ x,
                const float* __restrict__ U,
                float* __restrict__ out)
{
    extern __shared__ float smem[];
    float* Us = smem;                 // [128][128] swizzled
    float* xL = smem + 128 * 128;     // [128][128] swizzled
    float* P  = xL   + 128 * 128;     // [128][128] swizzled

    const int b  = blockIdx.y;
    const int c0 = blockIdx.x * CT;

    const int tid = threadIdx.x;
    const int tx  = tid & 15;         // owns l/d cols {4tx+q + 64jq}
    const int ty  = tid >> 4;         // owns c rows {8ty+i}

    // ---- load U tile (swizzled, float4) ----
    for (int idx = tid; idx < 128 * 32; idx += THREADS) {
        int r  = idx >> 5;
        int g  = idx & 31;
        int c  = c0 + r;
        float4 v = make_float4(0.f, 0.f, 0.f, 0.f);
        if (c < NCLS) v = ((const float4*)(U + (size_t)c * DIM))[g];
        *(float4*)(Us + swoff(r, g)) = v;
    }

    u64 O2[8][4];                     // [i][jp]: d pairs (4tx+2jp, +1) / +64
    float row_max[8], row_sum[8];
    #pragma unroll
    for (int i = 0; i < 8; i++) {
        row_max[i] = -1e30f; row_sum[i] = 0.0f;
        #pragma unroll
        for (int jp = 0; jp < 4; jp++) O2[i][jp] = 0ull;
    }

    const float* xb = x + (size_t)b * SEQ * DIM;

    for (int ch = 0; ch < NCHUNK; ++ch) {
        const int l0 = ch * LT;
        const int lvalid = (SEQ - l0 < LT) ? (SEQ - l0) : LT;

        __syncthreads();

        // ---- load x chunk (swizzled, float4) ----
        for (int idx = tid; idx < 128 * 32; idx += THREADS) {
            int r = idx >> 5;
            int g = idx & 31;
            float4 v = make_float4(0.f, 0.f, 0.f, 0.f);
            if (r < lvalid)
                v = ((const float4*)(xb + (size_t)(l0 + r) * DIM))[g];
            *(float4*)(xL + swoff(r, g)) = v;
        }
        __syncthreads();

        // ---- S = Us @ xL^T : acc packed over adjacent-l pairs ----
        // S2[i][lp], lp = jq*2+h -> l pair (4tx+64jq+2h, 4tx+64jq+2h+1)
        u64 S2[8][4];
        #pragma unroll
        for (int i = 0; i < 8; i++)
            #pragma unroll
            for (int lp = 0; lp < 4; lp++) S2[i][lp] = 0ull;

        for (int k4 = 0; k4 < 32; k4++) {
            float4 Ua[8];
            #pragma unroll
            for (int i = 0; i < 8; i++)
                Ua[i] = *(const float4*)(Us + swoff(8 * ty + i, k4));
            float4 Xb[2][4];
            #pragma unroll
            for (int jq = 0; jq < 2; jq++)
                #pragma unroll
                for (int q = 0; q < 4; q++)
                    Xb[jq][q] = *(const float4*)(xL + swoff(4 * tx + 64 * jq + q, k4));

            #pragma unroll
            for (int kk = 0; kk < 4; kk++) {
                u64 bp[4];
                #pragma unroll
                for (int jq = 0; jq < 2; jq++)
                    #pragma unroll
                    for (int h = 0; h < 2; h++) {
                        const float* f0 = (const float*)&Xb[jq][2 * h];
                        const float* f1 = (const float*)&Xb[jq][2 * h + 1];
                        bp[jq * 2 + h] = pack2(f0[kk], f1[kk]);
                    }
                #pragma unroll
                for (int i = 0; i < 8; i++) {
                    u64 ar = rep2(((const float*)&Ua[i])[kk]);
                    #pragma unroll
                    for (int lp = 0; lp < 4; lp++)
                        fma2(S2[i][lp], ar, bp[lp]);
                }
            }
        }

        // ---- unpack, mask, online softmax ----
        float S[8][8];   // m = jq*4+q -> l = 4tx + 64jq + q
        #pragma unroll
        for (int i = 0; i < 8; i++)
            #pragma unroll
            for (int lp = 0; lp < 4; lp++) {
                int jq = lp >> 1, h = lp & 1;
                unpack2(S2[i][lp], S[i][jq * 4 + 2 * h], S[i][jq * 4 + 2 * h + 1]);
            }

        #pragma unroll
        for (int m = 0; m < 8; m++) {
            int l = 4 * tx + 64 * (m >> 2) + (m & 3);
            if (l >= lvalid) {
                #pragma unroll
                for (int i = 0; i < 8; i++) S[i][m] = -1e30f;
            }
        }

        #pragma unroll
        for (int i = 0; i < 8; i++) {
            float mloc = S[i][0];
            #pragma unroll
            for (int m = 1; m < 8; m++) mloc = fmaxf(mloc, S[i][m]);
            #pragma unroll
            for (int m = 1; m < 16; m <<= 1)
                mloc = fmaxf(mloc, __shfl_xor_sync(0xffffffffu, mloc, m));

            float mnew = fmaxf(row_max[i], mloc);
            float corr = __expf(row_max[i] - mnew);
            row_max[i] = mnew;

            float s = 0.0f;
            #pragma unroll
            for (int m = 0; m < 8; m++) {
                float p = __expf(S[i][m] - mnew);
                S[i][m] = p;
                s += p;
            }
            #pragma unroll
            for (int m = 1; m < 16; m <<= 1)
                s += __shfl_xor_sync(0xffffffffu, s, m);

            row_sum[i] = row_sum[i] * corr + s;

            u64 corr2 = rep2(corr);
            #pragma unroll
            for (int jp = 0; jp < 4; jp++) mul2(O2[i][jp], corr2);
        }

        // ---- write P (swizzled float4) ----
        #pragma unroll
        for (int i = 0; i < 8; i++)
            #pragma unroll
            for (int jq = 0; jq < 2; jq++) {
                float4 v = make_float4(S[i][jq * 4 + 0], S[i][jq * 4 + 1],
                                       S[i][jq * 4 + 2], S[i][jq * 4 + 3]);
                *(float4*)(P + swoff(8 * ty + i, tx + 16 * jq)) = v;
            }
        __syncthreads();

        // ---- O += P @ xL : b d-pairs are native u64 halves ----
        for (int l4 = 0; l4 < 32; l4++) {
            float4 Pa[8];
            #pragma unroll
            for (int i = 0; i < 8; i++)
                Pa[i] = *(const float4*)(P + swoff(8 * ty + i, l4));

            #pragma unroll
            for (int ll = 0; ll < 4; ll++) {
                int l = l4 * 4 + ll;
                ulonglong2 b0 = *(const ulonglong2*)(xL + swoff(l, tx));
                ulonglong2 b1 = *(const ulonglong2*)(xL + swoff(l, tx + 16));
                #pragma unroll
                for (int i = 0; i < 8; i++) {
                    u64 ar = rep2(((const float*)&Pa[i])[ll]);
                    fma2(O2[i][0], ar, b0.x);
                    fma2(O2[i][1], ar, b0.y);
                    fma2(O2[i][2], ar, b1.x);
                    fma2(O2[i][3], ar, b1.y);
                }
            }
        }
    }

    // ---- normalize + vectorized store ----
    #pragma unroll
    for (int i = 0; i < 8; i++) {
        int c = c0 + 8 * ty + i;
        if (c >= NCLS) continue;
        float inv = 1.0f / row_sum[i];
        float* orow = out + ((size_t)b * NCLS + c) * DIM;
        #pragma unroll
        for (int jq = 0; jq < 2; jq++) {
            float a0, a1, a2, a3;
            unpack2(O2[i][jq * 2 + 0], a0, a1);
            unpack2(O2[i][jq * 2 + 1], a2, a3);
            float4 v = make_float4(a0 * inv, a1 * inv, a2 * inv, a3 * inv);
            *(float4*)(orow + 4 * tx + 64 * jq) = v;
        }
    }
}

extern "C" void kernel_launch(void* const* d_in, const int* in_sizes, int n_in,
                              void* d_out, int out_size)
{
    const float* x = (const float*)d_in[0];
    const float* U = (const float*)d_in[1];
    float* out = (float*)d_out;

    cudaFuncSetAttribute(lwa_kernel,
                         cudaFuncAttributeMaxDynamicSharedMemorySize,
                         SMEM_BYTES);

    dim3 grid((NCLS + CT - 1) / CT, BATCH);
    lwa_kernel<<<grid, THREADS, SMEM_BYTES>>>(x, U, out);
}

// round 6
// speedup vs baseline: 3.7261x; 3.7261x over previous
#include <cuda_runtime.h>
#include <cuda_bf16.h>
#include <cstdint>

#define BATCH   8
#define SEQ     2500
#define DIM     128
#define NCLS    8921
#define CT      128
#define LT      128
#define NCHUNK  20
#define THREADS 256

typedef uint32_t u32;

// bf16 tile arrays: 128 rows x 136 bf16 (272 B padded stride)
#define ROWB 272
#define ARR  (128 * ROWB)        // 34816 B
#define SM_UHI 0
#define SM_ULO (ARR)
#define SM_XHI (2 * ARR)
#define SM_XLO (3 * ARR)
#define SMEM_BYTES (4 * ARR)     // 139264

__device__ __forceinline__ u32 smem_u32(const void* p) {
    u32 a;
    asm("{ .reg .u64 t; cvta.to.shared.u64 t, %1; cvt.u32.u64 %0, t; }" : "=r"(a) : "l"(p));
    return a;
}
__device__ __forceinline__ void ldmx4(u32* r, u32 addr) {
    asm volatile("ldmatrix.sync.aligned.m8n8.x4.shared.b16 {%0,%1,%2,%3}, [%4];"
                 : "=r"(r[0]), "=r"(r[1]), "=r"(r[2]), "=r"(r[3]) : "r"(addr));
}
__device__ __forceinline__ void ldmx4t(u32* r, u32 addr) {
    asm volatile("ldmatrix.sync.aligned.m8n8.x4.trans.shared.b16 {%0,%1,%2,%3}, [%4];"
                 : "=r"(r[0]), "=r"(r[1]), "=r"(r[2]), "=r"(r[3]) : "r"(addr));
}
__device__ __forceinline__ void mma_bf16(float* c, const u32* a, u32 b0, u32 b1) {
    asm volatile("mma.sync.aligned.m16n8k16.row.col.f32.bf16.bf16.f32 "
                 "{%0,%1,%2,%3}, {%4,%5,%6,%7}, {%8,%9}, {%0,%1,%2,%3};"
                 : "+f"(c[0]), "+f"(c[1]), "+f"(c[2]), "+f"(c[3])
                 : "r"(a[0]), "r"(a[1]), "r"(a[2]), "r"(a[3]), "r"(b0), "r"(b1));
}
__device__ __forceinline__ u32 pack_bf16(float lo, float hi) {
    u32 r;
    asm("cvt.rn.bf16x2.f32 %0, %1, %2;" : "=r"(r) : "f"(hi), "f"(lo));
    return r;
}

// split float4 -> hi/lo bf16 uint2 pairs, store to smem (byte offsets)
__device__ __forceinline__ void split_store(char* smem, int off_hi, int off_lo, float4 v) {
    __nv_bfloat16 h0 = __float2bfloat16(v.x), h1 = __float2bfloat16(v.y);
    __nv_bfloat16 h2 = __float2bfloat16(v.z), h3 = __float2bfloat16(v.w);
    float r0 = v.x - __bfloat162float(h0), r1 = v.y - __bfloat162float(h1);
    float r2 = v.z - __bfloat162float(h2), r3 = v.w - __bfloat162float(h3);
    uint2 wh, wl;
    wh.x = (u32)__bfloat16_as_ushort(h0) | ((u32)__bfloat16_as_ushort(h1) << 16);
    wh.y = (u32)__bfloat16_as_ushort(h2) | ((u32)__bfloat16_as_ushort(h3) << 16);
    wl.x = pack_bf16(r0, r1);
    wl.y = pack_bf16(r2, r3);
    *(uint2*)(smem + off_hi) = wh;
    *(uint2*)(smem + off_lo) = wl;
}

__global__ __launch_bounds__(THREADS, 1)
void lwa_mma_kernel(const float* __restrict__ x,
                    const float* __restrict__ U,
                    float* __restrict__ out)
{
    extern __shared__ char smem[];
    const u32 sb = smem_u32(smem);

    const int tid  = threadIdx.x;
    const int w    = tid >> 5;
    const int lane = tid & 31;
    const int g    = lane >> 2;      // group id: rows g, g+8 of warp tile
    const int tig  = lane & 3;       // thread in group: cols 2*tig, 2*tig+1

    const int b  = blockIdx.y;
    const int c0 = blockIdx.x * CT;

    // ---- load + split U tile [c][d] ----
    for (int idx = tid; idx < 128 * 32; idx += THREADS) {
        int r = idx >> 5, gq = idx & 31;
        int c = c0 + r;
        float4 v = make_float4(0.f, 0.f, 0.f, 0.f);
        if (c < NCLS) v = ((const float4*)(U + (size_t)c * DIM))[gq];
        split_store(smem, SM_UHI + r * ROWB + gq * 8, SM_ULO + r * ROWB + gq * 8, v);
    }

    float O[16][4];
    #pragma unroll
    for (int j = 0; j < 16; j++)
        #pragma unroll
        for (int q = 0; q < 4; q++) O[j][q] = 0.0f;
    float rs0 = 0.0f, rs1 = 0.0f;

    const float* xb = x + (size_t)b * SEQ * DIM;

    // precomputed ldmatrix lane-address components
    // GEMM1 A (U, non-trans): rows 16w + (lane&15), seg (lane>>4)*16B
    const u32 aU_row = (u32)((16 * w + (lane & 15)) * ROWB + (lane >> 4) * 16);
    // GEMM1 B (x, non-trans): rows 8*(2*jn2 + (lane>>4)) + (lane&7), seg ((lane>>3)&1)*16B
    const u32 bS_base = (u32)((8 * (lane >> 4) + (lane & 7)) * ROWB + ((lane >> 3) & 1) * 16);
    // GEMM2 B (x, trans): rows 16kb + ((lane>>3)&1)*8 + (lane&7), dseg (2*jn2 + (lane>>4))*16B
    const u32 bO_base = (u32)((((lane >> 3) & 1) * 8 + (lane & 7)) * ROWB + (lane >> 4) * 16);

    for (int ch = 0; ch < NCHUNK; ++ch) {
        const int l0 = ch * LT;
        const int lvalid = (SEQ - l0 < LT) ? (SEQ - l0) : LT;

        __syncthreads();   // protect x from previous-chunk readers

        // ---- load + split x chunk [l][d] ----
        for (int idx = tid; idx < 128 * 32; idx += THREADS) {
            int r = idx >> 5, gq = idx & 31;
            float4 v = make_float4(0.f, 0.f, 0.f, 0.f);
            if (r < lvalid) v = ((const float4*)(xb + (size_t)(l0 + r) * DIM))[gq];
            split_store(smem, SM_XHI + r * ROWB + gq * 8, SM_XLO + r * ROWB + gq * 8, v);
        }
        __syncthreads();

        // ---- GEMM1: S[c 16][l 128] = U . x^T  (split-bf16, 3 products) ----
        float S[16][4];
        #pragma unroll
        for (int j = 0; j < 16; j++)
            #pragma unroll
            for (int q = 0; q < 4; q++) S[j][q] = 0.0f;

        #pragma unroll
        for (int kb = 0; kb < 8; kb++) {
            u32 aHi[4], aLo[4];
            ldmx4(aHi, sb + SM_UHI + aU_row + kb * 32);
            ldmx4(aLo, sb + SM_ULO + aU_row + kb * 32);
            #pragma unroll
            for (int jn2 = 0; jn2 < 8; jn2++) {
                u32 bHi[4], bLo[4];
                u32 off = bS_base + (u32)(16 * jn2 * ROWB + kb * 32);
                ldmx4(bHi, sb + SM_XHI + off);
                ldmx4(bLo, sb + SM_XLO + off);
                mma_bf16(S[2 * jn2],     aHi, bHi[0], bHi[1]);
                mma_bf16(S[2 * jn2],     aHi, bLo[0], bLo[1]);
                mma_bf16(S[2 * jn2],     aLo, bHi[0], bHi[1]);
                mma_bf16(S[2 * jn2 + 1], aHi, bHi[2], bHi[3]);
                mma_bf16(S[2 * jn2 + 1], aHi, bLo[2], bLo[3]);
                mma_bf16(S[2 * jn2 + 1], aLo, bHi[2], bHi[3]);
            }
        }

        // ---- epilogue: exp, row sums, repack as GEMM2 A fragments ----
        u32 Ahi[8][4], Alo[8][4];
        #pragma unroll
        for (int j = 0; j < 16; j++) {
            float e[4];
            #pragma unroll
            for (int q = 0; q < 4; q++) {
                int l = 8 * j + 2 * tig + (q & 1);
                e[q] = (l < lvalid) ? __expf(S[j][q]) : 0.0f;
            }
            rs0 += e[0] + e[1];
            rs1 += e[2] + e[3];
            int kb = j >> 1, hf = (j & 1) << 1;
            __nv_bfloat16 h0 = __float2bfloat16(e[0]), h1 = __float2bfloat16(e[1]);
            __nv_bfloat16 h2 = __float2bfloat16(e[2]), h3 = __float2bfloat16(e[3]);
            Ahi[kb][hf]     = (u32)__bfloat16_as_ushort(h0) | ((u32)__bfloat16_as_ushort(h1) << 16);
            Ahi[kb][hf + 1] = (u32)__bfloat16_as_ushort(h2) | ((u32)__bfloat16_as_ushort(h3) << 16);
            Alo[kb][hf]     = pack_bf16(e[0] - __bfloat162float(h0), e[1] - __bfloat162float(h1));
            Alo[kb][hf + 1] = pack_bf16(e[2] - __bfloat162float(h2), e[3] - __bfloat162float(h3));
        }

        // ---- GEMM2: O[c 16][d 128] += P . x  (x read transposed via ldmatrix.trans) ----
        #pragma unroll
        for (int kb = 0; kb < 8; kb++) {
            #pragma unroll
            for (int jn2 = 0; jn2 < 8; jn2++) {
                u32 bHi[4], bLo[4];
                u32 off = bO_base + (u32)(16 * kb * ROWB + 2 * jn2 * 16);
                ldmx4t(bHi, sb + SM_XHI + off);
                ldmx4t(bLo, sb + SM_XLO + off);
                mma_bf16(O[2 * jn2],     Ahi[kb], bHi[0], bHi[1]);
                mma_bf16(O[2 * jn2],     Ahi[kb], bLo[0], bLo[1]);
                mma_bf16(O[2 * jn2],     Alo[kb], bHi[0], bHi[1]);
                mma_bf16(O[2 * jn2 + 1], Ahi[kb], bHi[2], bHi[3]);
                mma_bf16(O[2 * jn2 + 1], Ahi[kb], bLo[2], bLo[3]);
                mma_bf16(O[2 * jn2 + 1], Alo[kb], bHi[2], bHi[3]);
            }
        }
    }

    // ---- final: reduce row sums across quad, normalize, store ----
    rs0 += __shfl_xor_sync(0xffffffffu, rs0, 1);
    rs0 += __shfl_xor_sync(0xffffffffu, rs0, 2);
    rs1 += __shfl_xor_sync(0xffffffffu, rs1, 1);
    rs1 += __shfl_xor_sync(0xffffffffu, rs1, 2);
    float inv0 = 1.0f / rs0, inv1 = 1.0f / rs1;

    int c_row0 = c0 + 16 * w + g;
    int c_row1 = c_row0 + 8;
    float* orow0 = out + ((size_t)b * NCLS + c_row0) * DIM;
    float* orow1 = out + ((size_t)b * NCLS + c_row1) * DIM;
    #pragma unroll
    for (int j = 0; j < 16; j++) {
        int d = 8 * j + 2 * tig;
        if (c_row0 < NCLS)
            *(float2*)(orow0 + d) = make_float2(O[j][0] * inv0, O[j][1] * inv0);
        if (c_row1 < NCLS)
            *(float2*)(orow1 + d) = make_float2(O[j][2] * inv1, O[j][3] * inv1);
    }
}

extern "C" void kernel_launch(void* const* d_in, const int* in_sizes, int n_in,
                              void* d_out, int out_size)
{
    const float* x = (const float*)d_in[0];   // [8, 2500, 128]
    const float* U = (const float*)d_in[1];   // [8921, 128]
    float* out = (float*)d_out;               // [8, 8921, 128]

    cudaFuncSetAttribute(lwa_mma_kernel,
                         cudaFuncAttributeMaxDynamicSharedMemorySize, SMEM_BYTES);

    dim3 grid((NCLS + CT - 1) / CT, BATCH);   // (70, 8)
    lwa_mma_kernel<<<grid, THREADS, SMEM_BYTES>>>(x, U, out);
}

// round 10
// speedup vs baseline: 3.9504x; 1.0602x over previous
#include <cuda_runtime.h>
#include <cuda_bf16.h>
#include <cstdint>

#define BATCH   8
#define SEQ     2500
#define LPAD    2560          // 20 chunks of 128
#define DIM     128
#define NCLS    8921
#define CPAD    8960          // 70 tiles of 128
#define CT      128
#define LT      128
#define NCHUNK  20
#define THREADS 256

typedef uint32_t u32;

// ---- global pre-split bf16 scratch ----
__device__ __nv_bfloat16 g_xhi[BATCH * LPAD * DIM];
__device__ __nv_bfloat16 g_xlo[BATCH * LPAD * DIM];
__device__ __nv_bfloat16 g_uhi[CPAD * DIM];
__device__ __nv_bfloat16 g_ulo[CPAD * DIM];

// ---- smem: U hi/lo + 2 x-buffers (hi/lo each) ----
#define ROWB 272                  // padded row stride bytes (128 bf16 -> 256B + 16B pad)
#define ARR  (128 * ROWB)         // 34816
#define SM_UHI 0
#define SM_ULO ARR
#define SM_X   (2 * ARR)
#define XBUF   (2 * ARR)          // hi+lo per buffer
#define SMEM_BYTES (2 * ARR + 2 * XBUF)   // 208896

__device__ __forceinline__ u32 smem_u32(const void* p) {
    u32 a;
    asm("{ .reg .u64 t; cvta.to.shared.u64 t, %1; cvt.u32.u64 %0, t; }" : "=r"(a) : "l"(p));
    return a;
}
__device__ __forceinline__ void cp16(u32 dst, const void* src) {
    asm volatile("cp.async.cg.shared.global [%0], [%1], 16;" :: "r"(dst), "l"(src) : "memory");
}
#define CP_COMMIT() asm volatile("cp.async.commit_group;" ::: "memory")
#define CP_WAIT0()  asm volatile("cp.async.wait_group 0;" ::: "memory")

__device__ __forceinline__ void ldmx4(u32* r, u32 addr) {
    asm volatile("ldmatrix.sync.aligned.m8n8.x4.shared.b16 {%0,%1,%2,%3}, [%4];"
                 : "=r"(r[0]), "=r"(r[1]), "=r"(r[2]), "=r"(r[3]) : "r"(addr));
}
__device__ __forceinline__ void ldmx4t(u32* r, u32 addr) {
    asm volatile("ldmatrix.sync.aligned.m8n8.x4.trans.shared.b16 {%0,%1,%2,%3}, [%4];"
                 : "=r"(r[0]), "=r"(r[1]), "=r"(r[2]), "=r"(r[3]) : "r"(addr));
}
__device__ __forceinline__ void mma_bf16(float* c, const u32* a, u32 b0, u32 b1) {
    asm volatile("mma.sync.aligned.m16n8k16.row.col.f32.bf16.bf16.f32 "
                 "{%0,%1,%2,%3}, {%4,%5,%6,%7}, {%8,%9}, {%0,%1,%2,%3};"
                 : "+f"(c[0]), "+f"(c[1]), "+f"(c[2]), "+f"(c[3])
                 : "r"(a[0]), "r"(a[1]), "r"(a[2]), "r"(a[3]), "r"(b0), "r"(b1));
}
__device__ __forceinline__ u32 pack_bf16(float lo, float hi) {
    u32 r;
    asm("cvt.rn.bf16x2.f32 %0, %1, %2;" : "=r"(r) : "f"(hi), "f"(lo));
    return r;
}

// ============ kernel 1: split fp32 -> bf16 hi/lo (x padded to LPAD, U to CPAD) ============
__global__ void split_kernel(const float* __restrict__ x, const float* __restrict__ U)
{
    const int NX = BATCH * LPAD * DIM / 4;   // float4 units
    const int NU = CPAD * DIM / 4;
    int idx = blockIdx.x * blockDim.x + threadIdx.x;

    float4 v = make_float4(0.f, 0.f, 0.f, 0.f);
    __nv_bfloat16* hi_arr;
    __nv_bfloat16* lo_arr;
    int dstq;

    if (idx < NX) {
        int b   = idx / (LPAD * DIM / 4);
        int rem = idx - b * (LPAD * DIM / 4);
        int l   = rem >> 5;                 // /32 float4 per row
        int q   = rem & 31;
        if (l < SEQ)
            v = ((const float4*)x)[((size_t)b * SEQ + l) * 32 + q];
        hi_arr = g_xhi; lo_arr = g_xlo; dstq = idx;
    } else if (idx < NX + NU) {
        int j = idx - NX;
        int c = j >> 5;
        int q = j & 31;
        if (c < NCLS)
            v = ((const float4*)U)[(size_t)c * 32 + q];
        hi_arr = g_uhi; lo_arr = g_ulo; dstq = j;
    } else return;

    __nv_bfloat16 h0 = __float2bfloat16(v.x), h1 = __float2bfloat16(v.y);
    __nv_bfloat16 h2 = __float2bfloat16(v.z), h3 = __float2bfloat16(v.w);
    uint2 wh, wl;
    wh.x = (u32)__bfloat16_as_ushort(h0) | ((u32)__bfloat16_as_ushort(h1) << 16);
    wh.y = (u32)__bfloat16_as_ushort(h2) | ((u32)__bfloat16_as_ushort(h3) << 16);
    wl.x = pack_bf16(v.x - __bfloat162float(h0), v.y - __bfloat162float(h1));
    wl.y = pack_bf16(v.z - __bfloat162float(h2), v.w - __bfloat162float(h3));
    ((uint2*)hi_arr)[dstq] = wh;
    ((uint2*)lo_arr)[dstq] = wl;
}

// ============ kernel 2: fused label-wise attention ============
__global__ __launch_bounds__(THREADS, 1)
void lwa_mma_kernel(float* __restrict__ out)
{
    extern __shared__ char smem[];
    const u32 sb = smem_u32(smem);

    const int tid  = threadIdx.x;
    const int w    = tid >> 5;
    const int lane = tid & 31;
    const int g    = lane >> 2;
    const int tig  = lane & 3;

    const int b  = blockIdx.y;
    const int c0 = blockIdx.x * CT;

    // ---- prefetch U tile + x chunk 0 (one cp.async group) ----
    {
        const __nv_bfloat16* uh = g_uhi + (size_t)c0 * DIM;
        const __nv_bfloat16* ul = g_ulo + (size_t)c0 * DIM;
        for (int idx = tid; idx < 128 * 16; idx += THREADS) {
            int r = idx >> 4, gq = idx & 15;
            u32 off = (u32)(r * ROWB + gq * 16);
            cp16(sb + SM_UHI + off, uh + r * DIM + gq * 8);
            cp16(sb + SM_ULO + off, ul + r * DIM + gq * 8);
        }
        const __nv_bfloat16* xh = g_xhi + (size_t)b * LPAD * DIM;
        const __nv_bfloat16* xl = g_xlo + (size_t)b * LPAD * DIM;
        for (int idx = tid; idx < 128 * 16; idx += THREADS) {
            int r = idx >> 4, gq = idx & 15;
            u32 off = (u32)(r * ROWB + gq * 16);
            cp16(sb + SM_X + off,       xh + r * DIM + gq * 8);
            cp16(sb + SM_X + ARR + off, xl + r * DIM + gq * 8);
        }
        CP_COMMIT();
    }

    float O[16][4];
    #pragma unroll
    for (int j = 0; j < 16; j++)
        #pragma unroll
        for (int q = 0; q < 4; q++) O[j][q] = 0.0f;
    float rs0 = 0.0f, rs1 = 0.0f;

    // ldmatrix lane-address components
    const u32 aU_row  = (u32)((16 * w + (lane & 15)) * ROWB + (lane >> 4) * 16);
    const u32 bS_base = (u32)((8 * (lane >> 4) + (lane & 7)) * ROWB + ((lane >> 3) & 1) * 16);
    const u32 bO_base = (u32)((((lane >> 3) & 1) * 8 + (lane & 7)) * ROWB + (lane >> 4) * 16);

    const __nv_bfloat16* xh_b = g_xhi + (size_t)b * LPAD * DIM;
    const __nv_bfloat16* xl_b = g_xlo + (size_t)b * LPAD * DIM;

    for (int ch = 0; ch < NCHUNK; ++ch) {
        const int l0 = ch * LT;
        const int lvalid = (SEQ - l0 < LT) ? (SEQ - l0) : LT;

        CP_WAIT0();
        __syncthreads();

        // ---- prefetch next chunk into the other buffer ----
        if (ch + 1 < NCHUNK) {
            const __nv_bfloat16* xh = xh_b + (size_t)(ch + 1) * LT * DIM;
            const __nv_bfloat16* xl = xl_b + (size_t)(ch + 1) * LT * DIM;
            u32 xbuf = sb + SM_X + ((ch + 1) & 1) * XBUF;
            for (int idx = tid; idx < 128 * 16; idx += THREADS) {
                int r = idx >> 4, gq = idx & 15;
                u32 off = (u32)(r * ROWB + gq * 16);
                cp16(xbuf + off,       xh + r * DIM + gq * 8);
                cp16(xbuf + ARR + off, xl + r * DIM + gq * 8);
            }
            CP_COMMIT();
        }

        const u32 xHi = sb + SM_X + (ch & 1) * XBUF;
        const u32 xLo = xHi + ARR;

        // ---- GEMM1: S = U . x^T  (3-product split bf16) ----
        float S[16][4];
        #pragma unroll
        for (int j = 0; j < 16; j++)
            #pragma unroll
            for (int q = 0; q < 4; q++) S[j][q] = 0.0f;

        #pragma unroll
        for (int kb = 0; kb < 8; kb++) {
            u32 aHi[4], aLo[4];
            ldmx4(aHi, sb + SM_UHI + aU_row + kb * 32);
            ldmx4(aLo, sb + SM_ULO + aU_row + kb * 32);
            #pragma unroll
            for (int jn2 = 0; jn2 < 8; jn2++) {
                u32 bHi[4], bLo[4];
                u32 off = bS_base + (u32)(16 * jn2 * ROWB + kb * 32);
                ldmx4(bHi, xHi + off);
                ldmx4(bLo, xLo + off);
                mma_bf16(S[2 * jn2],     aHi, bHi[0], bHi[1]);
                mma_bf16(S[2 * jn2],     aHi, bLo[0], bLo[1]);
                mma_bf16(S[2 * jn2],     aLo, bHi[0], bHi[1]);
                mma_bf16(S[2 * jn2 + 1], aHi, bHi[2], bHi[3]);
                mma_bf16(S[2 * jn2 + 1], aHi, bLo[2], bLo[3]);
                mma_bf16(S[2 * jn2 + 1], aLo, bHi[2], bHi[3]);
            }
        }

        // ---- fused epilogue + GEMM2: per k-block exp/pack then 48 MMAs ----
        #pragma unroll
        for (int kb = 0; kb < 8; kb++) {
            u32 Ahi[4], Alo[4];
            #pragma unroll
            for (int jj = 0; jj < 2; jj++) {
                int j = 2 * kb + jj;
                float e[4];
                #pragma unroll
                for (int q = 0; q < 4; q++) {
                    int l = 8 * j + 2 * tig + (q & 1);
                    e[q] = (l < lvalid) ? __expf(S[j][q]) : 0.0f;
                }
                rs0 += e[0] + e[1];
                rs1 += e[2] + e[3];
                __nv_bfloat16 h0 = __float2bfloat16(e[0]), h1 = __float2bfloat16(e[1]);
                __nv_bfloat16 h2 = __float2bfloat16(e[2]), h3 = __float2bfloat16(e[3]);
                Ahi[2 * jj]     = (u32)__bfloat16_as_ushort(h0) | ((u32)__bfloat16_as_ushort(h1) << 16);
                Ahi[2 * jj + 1] = (u32)__bfloat16_as_ushort(h2) | ((u32)__bfloat16_as_ushort(h3) << 16);
                Alo[2 * jj]     = pack_bf16(e[0] - __bfloat162float(h0), e[1] - __bfloat162float(h1));
                Alo[2 * jj + 1] = pack_bf16(e[2] - __bfloat162float(h2), e[3] - __bfloat162float(h3));
            }
            #pragma unroll
            for (int jn2 = 0; jn2 < 8; jn2++) {
                u32 bHi[4], bLo[4];
                u32 off = bO_base + (u32)(16 * kb * ROWB + 2 * jn2 * 16);
                ldmx4t(bHi, xHi + off);
                ldmx4t(bLo, xLo + off);
                mma_bf16(O[2 * jn2],     Ahi, bHi[0], bHi[1]);
                mma_bf16(O[2 * jn2],     Ahi, bLo[0], bLo[1]);
                mma_bf16(O[2 * jn2],     Alo, bHi[0], bHi[1]);
                mma_bf16(O[2 * jn2 + 1], Ahi, bHi[2], bHi[3]);
                mma_bf16(O[2 * jn2 + 1], Ahi, bLo[2], bLo[3]);
                mma_bf16(O[2 * jn2 + 1], Alo, bHi[2], bHi[3]);
            }
        }
    }

    // ---- reduce row sums across quad, normalize, store ----
    rs0 += __shfl_xor_sync(0xffffffffu, rs0, 1);
    rs0 += __shfl_xor_sync(0xffffffffu, rs0, 2);
    rs1 += __shfl_xor_sync(0xffffffffu, rs1, 1);
    rs1 += __shfl_xor_sync(0xffffffffu, rs1, 2);
    float inv0 = 1.0f / rs0, inv1 = 1.0f / rs1;

    int c_row0 = c0 + 16 * w + g;
    int c_row1 = c_row0 + 8;
    float* orow0 = out + ((size_t)b * NCLS + c_row0) * DIM;
    float* orow1 = out + ((size_t)b * NCLS + c_row1) * DIM;
    #pragma unroll
    for (int j = 0; j < 16; j++) {
        int d = 8 * j + 2 * tig;
        if (c_row0 < NCLS)
            *(float2*)(orow0 + d) = make_float2(O[j][0] * inv0, O[j][1] * inv0);
        if (c_row1 < NCLS)
            *(float2*)(orow1 + d) = make_float2(O[j][2] * inv1, O[j][3] * inv1);
    }
}

extern "C" void kernel_launch(void* const* d_in, const int* in_sizes, int n_in,
                              void* d_out, int out_size)
{
    const float* x = (const float*)d_in[0];   // [8, 2500, 128]
    const float* U = (const float*)d_in[1];   // [8921, 128]
    float* out = (float*)d_out;               // [8, 8921, 128]

    // kernel 1: split fp32 -> bf16 hi/lo scratch
    const int NTOT = BATCH * LPAD * DIM / 4 + CPAD * DIM / 4;
    split_kernel<<<(NTOT + 255) / 256, 256>>>(x, U);

    // kernel 2: fused attention
    cudaFuncSetAttribute(lwa_mma_kernel,
                         cudaFuncAttributeMaxDynamicSharedMemorySize, SMEM_BYTES);
    dim3 grid((NCLS + CT - 1) / CT, BATCH);   // (70, 8)
    lwa_mma_kernel<<<grid, THREADS, SMEM_BYTES>>>(out);
}

// round 13
// speedup vs baseline: 5.7560x; 1.4571x over previous
#include <cuda_runtime.h>
#include <cuda_fp16.h>
#include <cstdint>

#define BATCH   8
#define SEQ     2500
#define LPAD    2560          // 20 chunks of 128
#define DIM     128
#define NCLS    8921
#define CPAD    8960          // 70 tiles of 128
#define CT      128
#define LT      128
#define NCHUNK  20
#define THREADS 256

typedef uint32_t u32;

// ---- global pre-split fp16 scratch ----
__device__ __half g_xh [BATCH * LPAD * DIM];   // x single fp16
__device__ __half g_uhi[CPAD * DIM];           // U hi
__device__ __half g_ulo[CPAD * DIM];           // U lo

// ---- smem: U hi/lo + 2 x-buffers ----
#define ROWB 272                  // padded row stride bytes
#define ARR  (128 * ROWB)         // 34816
#define SM_UHI 0
#define SM_ULO ARR
#define SM_X   (2 * ARR)
#define SMEM_BYTES (2 * ARR + 2 * ARR)   // 139264

__device__ __forceinline__ u32 smem_u32(const void* p) {
    u32 a;
    asm("{ .reg .u64 t; cvta.to.shared.u64 t, %1; cvt.u32.u64 %0, t; }" : "=r"(a) : "l"(p));
    return a;
}
__device__ __forceinline__ void cp16(u32 dst, const void* src) {
    asm volatile("cp.async.cg.shared.global [%0], [%1], 16;" :: "r"(dst), "l"(src) : "memory");
}
#define CP_COMMIT() asm volatile("cp.async.commit_group;" ::: "memory")
#define CP_WAIT0()  asm volatile("cp.async.wait_group 0;" ::: "memory")

__device__ __forceinline__ void ldmx4(u32* r, u32 addr) {
    asm volatile("ldmatrix.sync.aligned.m8n8.x4.shared.b16 {%0,%1,%2,%3}, [%4];"
                 : "=r"(r[0]), "=r"(r[1]), "=r"(r[2]), "=r"(r[3]) : "r"(addr));
}
__device__ __forceinline__ void ldmx4t(u32* r, u32 addr) {
    asm volatile("ldmatrix.sync.aligned.m8n8.x4.trans.shared.b16 {%0,%1,%2,%3}, [%4];"
                 : "=r"(r[0]), "=r"(r[1]), "=r"(r[2]), "=r"(r[3]) : "r"(addr));
}
__device__ __forceinline__ void mma_f16(float* c, const u32* a, u32 b0, u32 b1) {
    asm volatile("mma.sync.aligned.m16n8k16.row.col.f32.f16.f16.f32 "
                 "{%0,%1,%2,%3}, {%4,%5,%6,%7}, {%8,%9}, {%0,%1,%2,%3};"
                 : "+f"(c[0]), "+f"(c[1]), "+f"(c[2]), "+f"(c[3])
                 : "r"(a[0]), "r"(a[1]), "r"(a[2]), "r"(a[3]), "r"(b0), "r"(b1));
}
__device__ __forceinline__ u32 pack2h(__half a, __half b) {   // a -> low half
    return (u32)__half_as_ushort(a) | ((u32)__half_as_ushort(b) << 16);
}

// ============ kernel 1: fp32 -> fp16 (x single; U hi/lo), padded ============
__global__ void split_kernel(const float* __restrict__ x, const float* __restrict__ U)
{
    const int NX = BATCH * LPAD * DIM / 4;   // float4 units
    const int NU = CPAD * DIM / 4;
    int idx = blockIdx.x * blockDim.x + threadIdx.x;

    if (idx < NX) {
        int b   = idx / (LPAD * DIM / 4);
        int rem = idx - b * (LPAD * DIM / 4);
        int l   = rem >> 5;
        int q   = rem & 31;
        float4 v = make_float4(0.f, 0.f, 0.f, 0.f);
        if (l < SEQ)
            v = ((const float4*)x)[((size_t)b * SEQ + l) * 32 + q];
        uint2 w;
        w.x = pack2h(__float2half_rn(v.x), __float2half_rn(v.y));
        w.y = pack2h(__float2half_rn(v.z), __float2half_rn(v.w));
        ((uint2*)g_xh)[idx] = w;
    } else if (idx < NX + NU) {
        int j = idx - NX;
        int c = j >> 5;
        int q = j & 31;
        float4 v = make_float4(0.f, 0.f, 0.f, 0.f);
        if (c < NCLS)
            v = ((const float4*)U)[(size_t)c * 32 + q];
        __half h0 = __float2half_rn(v.x), h1 = __float2half_rn(v.y);
        __half h2 = __float2half_rn(v.z), h3 = __float2half_rn(v.w);
        uint2 wh, wl;
        wh.x = pack2h(h0, h1);
        wh.y = pack2h(h2, h3);
        wl.x = pack2h(__float2half_rn(v.x - __half2float(h0)),
                      __float2half_rn(v.y - __half2float(h1)));
        wl.y = pack2h(__float2half_rn(v.z - __half2float(h2)),
                      __float2half_rn(v.w - __half2float(h3)));
        ((uint2*)g_uhi)[j] = wh;
        ((uint2*)g_ulo)[j] = wl;
    }
}

// ============ kernel 2: fused label-wise attention ============
__global__ __launch_bounds__(THREADS, 1)
void lwa_mma_kernel(float* __restrict__ out)
{
    extern __shared__ char smem[];
    const u32 sb = smem_u32(smem);

    const int tid  = threadIdx.x;
    const int w    = tid >> 5;
    const int lane = tid & 31;
    const int g    = lane >> 2;
    const int tig  = lane & 3;

    const int b  = blockIdx.y;
    const int c0 = blockIdx.x * CT;

    // ---- prefetch U tile (hi+lo) + x chunk 0 ----
    {
        const __half* uh = g_uhi + (size_t)c0 * DIM;
        const __half* ul = g_ulo + (size_t)c0 * DIM;
        const __half* xh = g_xh + (size_t)b * LPAD * DIM;
        for (int idx = tid; idx < 128 * 16; idx += THREADS) {
            int r = idx >> 4, gq = idx & 15;
            u32 off = (u32)(r * ROWB + gq * 16);
            cp16(sb + SM_UHI + off, uh + r * DIM + gq * 8);
            cp16(sb + SM_ULO + off, ul + r * DIM + gq * 8);
            cp16(sb + SM_X   + off, xh + r * DIM + gq * 8);
        }
        CP_COMMIT();
    }

    float O[16][4];
    #pragma unroll
    for (int j = 0; j < 16; j++)
        #pragma unroll
        for (int q = 0; q < 4; q++) O[j][q] = 0.0f;
    float rs0 = 0.0f, rs1 = 0.0f;

    const u32 aU_row  = (u32)((16 * w + (lane & 15)) * ROWB + (lane >> 4) * 16);
    const u32 bS_base = (u32)((8 * (lane >> 4) + (lane & 7)) * ROWB + ((lane >> 3) & 1) * 16);
    const u32 bO_base = (u32)((((lane >> 3) & 1) * 8 + (lane & 7)) * ROWB + (lane >> 4) * 16);

    const __half* xh_b = g_xh + (size_t)b * LPAD * DIM;

    for (int ch = 0; ch < NCHUNK; ++ch) {
        const int l0 = ch * LT;
        const int lvalid = (SEQ - l0 < LT) ? (SEQ - l0) : LT;

        CP_WAIT0();
        __syncthreads();

        // ---- prefetch next chunk ----
        if (ch + 1 < NCHUNK) {
            const __half* xh = xh_b + (size_t)(ch + 1) * LT * DIM;
            u32 xbuf = sb + SM_X + ((ch + 1) & 1) * ARR;
            for (int idx = tid; idx < 128 * 16; idx += THREADS) {
                int r = idx >> 4, gq = idx & 15;
                cp16(xbuf + (u32)(r * ROWB + gq * 16), xh + r * DIM + gq * 8);
            }
            CP_COMMIT();
        }

        const u32 xS = sb + SM_X + (ch & 1) * ARR;

        // ---- GEMM1: S = U . x^T  (2-product: Uhi*x + Ulo*x) ----
        float S[16][4];
        #pragma unroll
        for (int j = 0; j < 16; j++)
            #pragma unroll
            for (int q = 0; q < 4; q++) S[j][q] = 0.0f;

        #pragma unroll
        for (int kb = 0; kb < 8; kb++) {
            u32 aHi[4], aLo[4];
            ldmx4(aHi, sb + SM_UHI + aU_row + kb * 32);
            ldmx4(aLo, sb + SM_ULO + aU_row + kb * 32);
            #pragma unroll
            for (int jn2 = 0; jn2 < 8; jn2++) {
                u32 bX[4];
                ldmx4(bX, xS + bS_base + (u32)(16 * jn2 * ROWB + kb * 32));
                mma_f16(S[2 * jn2],     aHi, bX[0], bX[1]);
                mma_f16(S[2 * jn2],     aLo, bX[0], bX[1]);
                mma_f16(S[2 * jn2 + 1], aHi, bX[2], bX[3]);
                mma_f16(S[2 * jn2 + 1], aLo, bX[2], bX[3]);
            }
        }

        // ---- fused epilogue + GEMM2: per k-block exp/split-pack then MMAs ----
        #pragma unroll
        for (int kb = 0; kb < 8; kb++) {
            u32 Ahi[4], Alo[4];
            #pragma unroll
            for (int jj = 0; jj < 2; jj++) {
                int j = 2 * kb + jj;
                float e[4];
                #pragma unroll
                for (int q = 0; q < 4; q++) {
                    int l = 8 * j + 2 * tig + (q & 1);
                    e[q] = (l < lvalid) ? __expf(S[j][q]) : 0.0f;
                }
                rs0 += e[0] + e[1];
                rs1 += e[2] + e[3];
                __half h0 = __float2half_rn(e[0]), h1 = __float2half_rn(e[1]);
                __half h2 = __float2half_rn(e[2]), h3 = __float2half_rn(e[3]);
                Ahi[2 * jj]     = pack2h(h0, h1);
                Ahi[2 * jj + 1] = pack2h(h2, h3);
                Alo[2 * jj]     = pack2h(__float2half_rn(e[0] - __half2float(h0)),
                                         __float2half_rn(e[1] - __half2float(h1)));
                Alo[2 * jj + 1] = pack2h(__float2half_rn(e[2] - __half2float(h2)),
                                         __float2half_rn(e[3] - __half2float(h3)));
            }
            #pragma unroll
            for (int jn2 = 0; jn2 < 8; jn2++) {
                u32 bX[4];
                ldmx4t(bX, xS + bO_base + (u32)(16 * kb * ROWB + 2 * jn2 * 16));
                mma_f16(O[2 * jn2],     Ahi, bX[0], bX[1]);
                mma_f16(O[2 * jn2],     Alo, bX[0], bX[1]);
                mma_f16(O[2 * jn2 + 1], Ahi, bX[2], bX[3]);
                mma_f16(O[2 * jn2 + 1], Alo, bX[2], bX[3]);
            }
        }
    }

    // ---- reduce row sums across quad, normalize, store ----
    rs0 += __shfl_xor_sync(0xffffffffu, rs0, 1);
    rs0 += __shfl_xor_sync(0xffffffffu, rs0, 2);
    rs1 += __shfl_xor_sync(0xffffffffu, rs1, 1);
    rs1 += __shfl_xor_sync(0xffffffffu, rs1, 2);
    float inv0 = 1.0f / rs0, inv1 = 1.0f / rs1;

    int c_row0 = c0 + 16 * w + g;
    int c_row1 = c_row0 + 8;
    float* orow0 = out + ((size_t)b * NCLS + c_row0) * DIM;
    float* orow1 = out + ((size_t)b * NCLS + c_row1) * DIM;
    #pragma unroll
    for (int j = 0; j < 16; j++) {
        int d = 8 * j + 2 * tig;
        if (c_row0 < NCLS)
            *(float2*)(orow0 + d) = make_float2(O[j][0] * inv0, O[j][1] * inv0);
        if (c_row1 < NCLS)
            *(float2*)(orow1 + d) = make_float2(O[j][2] * inv1, O[j][3] * inv1);
    }
}

extern "C" void kernel_launch(void* const* d_in, const int* in_sizes, int n_in,
                              void* d_out, int out_size)
{
    const float* x = (const float*)d_in[0];   // [8, 2500, 128]
    const float* U = (const float*)d_in[1];   // [8921, 128]
    float* out = (float*)d_out;               // [8, 8921, 128]

    const int NTOT = BATCH * LPAD * DIM / 4 + CPAD * DIM / 4;
    split_kernel<<<(NTOT + 255) / 256, 256>>>(x, U);

    cudaFuncSetAttribute(lwa_mma_kernel,
                         cudaFuncAttributeMaxDynamicSharedMemorySize, SMEM_BYTES);
    dim3 grid((NCLS + CT - 1) / CT, BATCH);   // (70, 8)
    lwa_mma_kernel<<<grid, THREADS, SMEM_BYTES>>>(out);
}

// round 14
// speedup vs baseline: 9.5043x; 1.6512x over previous
#include <cuda_runtime.h>
#include <cuda_fp16.h>
#include <cstdint>

#define BATCH   8
#define SEQ     2500
#define LPAD    2560          // 20 chunks of 128
#define DIM     128
#define NCLS    8921
#define CPAD    8960          // 70 tiles of 128
#define CT      128
#define LT      128
#define NCHUNK  20
#define THREADS 256

typedef uint32_t u32;

// ---- global fp16 scratch ----
__device__ __half g_xh[BATCH * LPAD * DIM];   // x fp16
__device__ __half g_uh[CPAD * DIM];           // U fp16

// ---- smem: U + 2 x-buffers ----
#define ROWB 272                  // padded row stride bytes
#define ARR  (128 * ROWB)         // 34816
#define SM_U 0
#define SM_X ARR
#define SMEM_BYTES (3 * ARR)      // 104448

__device__ __forceinline__ u32 smem_u32(const void* p) {
    u32 a;
    asm("{ .reg .u64 t; cvta.to.shared.u64 t, %1; cvt.u32.u64 %0, t; }" : "=r"(a) : "l"(p));
    return a;
}
__device__ __forceinline__ void cp16(u32 dst, const void* src) {
    asm volatile("cp.async.cg.shared.global [%0], [%1], 16;" :: "r"(dst), "l"(src) : "memory");
}
#define CP_COMMIT() asm volatile("cp.async.commit_group;" ::: "memory")
#define CP_WAIT0()  asm volatile("cp.async.wait_group 0;" ::: "memory")

__device__ __forceinline__ void ldmx4(u32* r, u32 addr) {
    asm volatile("ldmatrix.sync.aligned.m8n8.x4.shared.b16 {%0,%1,%2,%3}, [%4];"
                 : "=r"(r[0]), "=r"(r[1]), "=r"(r[2]), "=r"(r[3]) : "r"(addr));
}
__device__ __forceinline__ void ldmx4t(u32* r, u32 addr) {
    asm volatile("ldmatrix.sync.aligned.m8n8.x4.trans.shared.b16 {%0,%1,%2,%3}, [%4];"
                 : "=r"(r[0]), "=r"(r[1]), "=r"(r[2]), "=r"(r[3]) : "r"(addr));
}
__device__ __forceinline__ void mma_f16(float* c, const u32* a, u32 b0, u32 b1) {
    asm volatile("mma.sync.aligned.m16n8k16.row.col.f32.f16.f16.f32 "
                 "{%0,%1,%2,%3}, {%4,%5,%6,%7}, {%8,%9}, {%0,%1,%2,%3};"
                 : "+f"(c[0]), "+f"(c[1]), "+f"(c[2]), "+f"(c[3])
                 : "r"(a[0]), "r"(a[1]), "r"(a[2]), "r"(a[3]), "r"(b0), "r"(b1));
}
__device__ __forceinline__ u32 pack2h(__half a, __half b) {
    return (u32)__half_as_ushort(a) | ((u32)__half_as_ushort(b) << 16);
}

// ============ kernel 1: fp32 -> fp16, padded ============
__global__ void split_kernel(const float* __restrict__ x, const float* __restrict__ U)
{
    const int NX = BATCH * LPAD * DIM / 4;   // float4 units
    const int NU = CPAD * DIM / 4;
    int idx = blockIdx.x * blockDim.x + threadIdx.x;

    if (idx < NX) {
        int b   = idx / (LPAD * DIM / 4);
        int rem = idx - b * (LPAD * DIM / 4);
        int l   = rem >> 5;
        int q   = rem & 31;
        float4 v = make_float4(0.f, 0.f, 0.f, 0.f);
        if (l < SEQ)
            v = ((const float4*)x)[((size_t)b * SEQ + l) * 32 + q];
        uint2 w;
        w.x = pack2h(__float2half_rn(v.x), __float2half_rn(v.y));
        w.y = pack2h(__float2half_rn(v.z), __float2half_rn(v.w));
        ((uint2*)g_xh)[idx] = w;
    } else if (idx < NX + NU) {
        int j = idx - NX;
        int c = j >> 5;
        int q = j & 31;
        float4 v = make_float4(0.f, 0.f, 0.f, 0.f);
        if (c < NCLS)
            v = ((const float4*)U)[(size_t)c * 32 + q];
        uint2 w;
        w.x = pack2h(__float2half_rn(v.x), __float2half_rn(v.y));
        w.y = pack2h(__float2half_rn(v.z), __float2half_rn(v.w));
        ((uint2*)g_uh)[j] = w;
    }
}

// ============ kernel 2: fused label-wise attention (plain fp16 MMA) ============
__global__ __launch_bounds__(THREADS, 1)
void lwa_mma_kernel(float* __restrict__ out)
{
    extern __shared__ char smem[];
    const u32 sb = smem_u32(smem);

    const int tid  = threadIdx.x;
    const int w    = tid >> 5;
    const int lane = tid & 31;
    const int g    = lane >> 2;
    const int tig  = lane & 3;

    const int b  = blockIdx.y;
    const int c0 = blockIdx.x * CT;

    // ---- prefetch U tile + x chunk 0 ----
    {
        const __half* uh = g_uh + (size_t)c0 * DIM;
        const __half* xh = g_xh + (size_t)b * LPAD * DIM;
        for (int idx = tid; idx < 128 * 16; idx += THREADS) {
            int r = idx >> 4, gq = idx & 15;
            u32 off = (u32)(r * ROWB + gq * 16);
            cp16(sb + SM_U + off, uh + r * DIM + gq * 8);
            cp16(sb + SM_X + off, xh + r * DIM + gq * 8);
        }
        CP_COMMIT();
    }

    float O[16][4];
    #pragma unroll
    for (int j = 0; j < 16; j++)
        #pragma unroll
        for (int q = 0; q < 4; q++) O[j][q] = 0.0f;
    float rs0 = 0.0f, rs1 = 0.0f;

    const u32 aU_row  = (u32)((16 * w + (lane & 15)) * ROWB + (lane >> 4) * 16);
    const u32 bS_base = (u32)((8 * (lane >> 4) + (lane & 7)) * ROWB + ((lane >> 3) & 1) * 16);
    const u32 bO_base = (u32)((((lane >> 3) & 1) * 8 + (lane & 7)) * ROWB + (lane >> 4) * 16);

    const __half* xh_b = g_xh + (size_t)b * LPAD * DIM;

    for (int ch = 0; ch < NCHUNK; ++ch) {
        const int l0 = ch * LT;
        const int lvalid = (SEQ - l0 < LT) ? (SEQ - l0) : LT;

        CP_WAIT0();
        __syncthreads();

        // ---- prefetch next chunk ----
        if (ch + 1 < NCHUNK) {
            const __half* xh = xh_b + (size_t)(ch + 1) * LT * DIM;
            u32 xbuf = sb + SM_X + ((ch + 1) & 1) * ARR;
            for (int idx = tid; idx < 128 * 16; idx += THREADS) {
                int r = idx >> 4, gq = idx & 15;
                cp16(xbuf + (u32)(r * ROWB + gq * 16), xh + r * DIM + gq * 8);
            }
            CP_COMMIT();
        }

        const u32 xS = sb + SM_X + (ch & 1) * ARR;

        // ---- GEMM1: S = U . x^T  (single fp16 product) ----
        float S[16][4];
        #pragma unroll
        for (int j = 0; j < 16; j++)
            #pragma unroll
            for (int q = 0; q < 4; q++) S[j][q] = 0.0f;

        #pragma unroll
        for (int kb = 0; kb < 8; kb++) {
            u32 aU[4];
            ldmx4(aU, sb + SM_U + aU_row + kb * 32);
            #pragma unroll
            for (int jn2 = 0; jn2 < 8; jn2++) {
                u32 bX[4];
                ldmx4(bX, xS + bS_base + (u32)(16 * jn2 * ROWB + kb * 32));
                mma_f16(S[2 * jn2],     aU, bX[0], bX[1]);
                mma_f16(S[2 * jn2 + 1], aU, bX[2], bX[3]);
            }
        }

        // ---- fused epilogue + GEMM2 (single fp16 product) ----
        #pragma unroll
        for (int kb = 0; kb < 8; kb++) {
            u32 Ap[4];
            #pragma unroll
            for (int jj = 0; jj < 2; jj++) {
                int j = 2 * kb + jj;
                float e[4];
                #pragma unroll
                for (int q = 0; q < 4; q++) {
                    int l = 8 * j + 2 * tig + (q & 1);
                    e[q] = (l < lvalid) ? __expf(S[j][q]) : 0.0f;
                }
                rs0 += e[0] + e[1];
                rs1 += e[2] + e[3];
                Ap[2 * jj]     = pack2h(__float2half_rn(e[0]), __float2half_rn(e[1]));
                Ap[2 * jj + 1] = pack2h(__float2half_rn(e[2]), __float2half_rn(e[3]));
            }
            #pragma unroll
            for (int jn2 = 0; jn2 < 8; jn2++) {
                u32 bX[4];
                ldmx4t(bX, xS + bO_base + (u32)(16 * kb * ROWB + 2 * jn2 * 16));
                mma_f16(O[2 * jn2],     Ap, bX[0], bX[1]);
                mma_f16(O[2 * jn2 + 1], Ap, bX[2], bX[3]);
            }
        }
    }

    // ---- reduce row sums across quad, normalize, store ----
    rs0 += __shfl_xor_sync(0xffffffffu, rs0, 1);
    rs0 += __shfl_xor_sync(0xffffffffu, rs0, 2);
    rs1 += __shfl_xor_sync(0xffffffffu, rs1, 1);
    rs1 += __shfl_xor_sync(0xffffffffu, rs1, 2);
    float inv0 = 1.0f / rs0, inv1 = 1.0f / rs1;

    int c_row0 = c0 + 16 * w + g;
    int c_row1 = c_row0 + 8;
    float* orow0 = out + ((size_t)b * NCLS + c_row0) * DIM;
    float* orow1 = out + ((size_t)b * NCLS + c_row1) * DIM;
    #pragma unroll
    for (int j = 0; j < 16; j++) {
        int d = 8 * j + 2 * tig;
        if (c_row0 < NCLS)
            *(float2*)(orow0 + d) = make_float2(O[j][0] * inv0, O[j][1] * inv0);
        if (c_row1 < NCLS)
            *(float2*)(orow1 + d) = make_float2(O[j][2] * inv1, O[j][3] * inv1);
    }
}

extern "C" void kernel_launch(void* const* d_in, const int* in_sizes, int n_in,
                              void* d_out, int out_size)
{
    const float* x = (const float*)d_in[0];   // [8, 2500, 128]
    const float* U = (const float*)d_in[1];   // [8921, 128]
    float* out = (float*)d_out;               // [8, 8921, 128]

    const int NTOT = BATCH * LPAD * DIM / 4 + CPAD * DIM / 4;
    split_kernel<<<(NTOT + 255) / 256, 256>>>(x, U);

    cudaFuncSetAttribute(lwa_mma_kernel,
                         cudaFuncAttributeMaxDynamicSharedMemorySize, SMEM_BYTES);
    dim3 grid((NCLS + CT - 1) / CT, BATCH);   // (70, 8)
    lwa_mma_kernel<<<grid, THREADS, SMEM_BYTES>>>(out);
}

// round 17
// speedup vs baseline: 9.7423x; 1.0250x over previous
#include <cuda_runtime.h>
#include <cuda_fp16.h>
#include <cstdint>

#define BATCH   8
#define SEQ     2500
#define LPAD    2560          // 20 chunks of 128
#define DIM     128
#define NCLS    8921
#define CPAD    8960          // 140 tiles of 64
#define CT      64
#define LT      128
#define NCHUNK  20
#define THREADS 128

typedef uint32_t u32;

// ---- global fp16 scratch ----
__device__ __half g_xh[BATCH * LPAD * DIM];   // x fp16
__device__ __half g_uh[CPAD * DIM];           // U fp16

// ---- smem: U (64 rows) + 2 x-buffers (128 rows each) ----
#define ROWB 272                  // padded row stride bytes
#define UARR (64 * ROWB)          // 17408
#define ARR  (128 * ROWB)         // 34816
#define SM_U 0
#define SM_X UARR
#define SMEM_BYTES (UARR + 2 * ARR)   // 87040

__device__ __forceinline__ u32 smem_u32(const void* p) {
    u32 a;
    asm("{ .reg .u64 t; cvta.to.shared.u64 t, %1; cvt.u32.u64 %0, t; }" : "=r"(a) : "l"(p));
    return a;
}
__device__ __forceinline__ void cp16(u32 dst, const void* src) {
    asm volatile("cp.async.cg.shared.global [%0], [%1], 16;" :: "r"(dst), "l"(src) : "memory");
}
#define CP_COMMIT() asm volatile("cp.async.commit_group;" ::: "memory")
#define CP_WAIT0()  asm volatile("cp.async.wait_group 0;" ::: "memory")

__device__ __forceinline__ void ldmx4(u32* r, u32 addr) {
    asm volatile("ldmatrix.sync.aligned.m8n8.x4.shared.b16 {%0,%1,%2,%3}, [%4];"
                 : "=r"(r[0]), "=r"(r[1]), "=r"(r[2]), "=r"(r[3]) : "r"(addr));
}
__device__ __forceinline__ void ldmx4t(u32* r, u32 addr) {
    asm volatile("ldmatrix.sync.aligned.m8n8.x4.trans.shared.b16 {%0,%1,%2,%3}, [%4];"
                 : "=r"(r[0]), "=r"(r[1]), "=r"(r[2]), "=r"(r[3]) : "r"(addr));
}
__device__ __forceinline__ void mma_f16(float* c, const u32* a, u32 b0, u32 b1) {
    asm volatile("mma.sync.aligned.m16n8k16.row.col.f32.f16.f16.f32 "
                 "{%0,%1,%2,%3}, {%4,%5,%6,%7}, {%8,%9}, {%0,%1,%2,%3};"
                 : "+f"(c[0]), "+f"(c[1]), "+f"(c[2]), "+f"(c[3])
                 : "r"(a[0]), "r"(a[1]), "r"(a[2]), "r"(a[3]), "r"(b0), "r"(b1));
}
__device__ __forceinline__ u32 pack2h(__half a, __half b) {
    return (u32)__half_as_ushort(a) | ((u32)__half_as_ushort(b) << 16);
}

// ============ kernel 1: fp32 -> fp16, padded ============
__global__ void split_kernel(const float* __restrict__ x, const float* __restrict__ U)
{
    const int NX = BATCH * LPAD * DIM / 4;   // float4 units
    const int NU = CPAD * DIM / 4;
    int idx = blockIdx.x * blockDim.x + threadIdx.x;

    if (idx < NX) {
        int b   = idx / (LPAD * DIM / 4);
        int rem = idx - b * (LPAD * DIM / 4);
        int l   = rem >> 5;
        int q   = rem & 31;
        float4 v = make_float4(0.f, 0.f, 0.f, 0.f);
        if (l < SEQ)
            v = ((const float4*)x)[((size_t)b * SEQ + l) * 32 + q];
        uint2 w;
        w.x = pack2h(__float2half_rn(v.x), __float2half_rn(v.y));
        w.y = pack2h(__float2half_rn(v.z), __float2half_rn(v.w));
        ((uint2*)g_xh)[idx] = w;
    } else if (idx < NX + NU) {
        int j = idx - NX;
        int c = j >> 5;
        int q = j & 31;
        float4 v = make_float4(0.f, 0.f, 0.f, 0.f);
        if (c < NCLS)
            v = ((const float4*)U)[(size_t)c * 32 + q];
        uint2 w;
        w.x = pack2h(__float2half_rn(v.x), __float2half_rn(v.y));
        w.y = pack2h(__float2half_rn(v.z), __float2half_rn(v.w));
        ((uint2*)g_uh)[j] = w;
    }
}

// ============ kernel 2: fused label-wise attention (2 CTAs/SM) ============
__global__ __launch_bounds__(THREADS, 2)
void lwa_mma_kernel(float* __restrict__ out)
{
    extern __shared__ char smem[];
    const u32 sb = smem_u32(smem);

    const int tid  = threadIdx.x;
    const int w    = tid >> 5;       // 0..3
    const int lane = tid & 31;
    const int g    = lane >> 2;
    const int tig  = lane & 3;

    const int b  = blockIdx.y;
    const int c0 = blockIdx.x * CT;

    // ---- prefetch U tile (64 rows) + x chunk 0 ----
    {
        const __half* uh = g_uh + (size_t)c0 * DIM;
        const __half* xh = g_xh + (size_t)b * LPAD * DIM;
        for (int idx = tid; idx < 64 * 16; idx += THREADS) {
            int r = idx >> 4, gq = idx & 15;
            cp16(sb + SM_U + (u32)(r * ROWB + gq * 16), uh + r * DIM + gq * 8);
        }
        for (int idx = tid; idx < 128 * 16; idx += THREADS) {
            int r = idx >> 4, gq = idx & 15;
            cp16(sb + SM_X + (u32)(r * ROWB + gq * 16), xh + r * DIM + gq * 8);
        }
        CP_COMMIT();
    }

    float O[16][4];
    #pragma unroll
    for (int j = 0; j < 16; j++)
        #pragma unroll
        for (int q = 0; q < 4; q++) O[j][q] = 0.0f;
    float rs0 = 0.0f, rs1 = 0.0f;

    const u32 aU_row  = (u32)((16 * w + (lane & 15)) * ROWB + (lane >> 4) * 16);
    const u32 bS_base = (u32)((8 * (lane >> 4) + (lane & 7)) * ROWB + ((lane >> 3) & 1) * 16);
    const u32 bO_base = (u32)((((lane >> 3) & 1) * 8 + (lane & 7)) * ROWB + (lane >> 4) * 16);

    const __half* xh_b = g_xh + (size_t)b * LPAD * DIM;

    for (int ch = 0; ch < NCHUNK; ++ch) {
        const int l0 = ch * LT;
        const int lvalid = (SEQ - l0 < LT) ? (SEQ - l0) : LT;

        CP_WAIT0();
        __syncthreads();

        // ---- prefetch next chunk ----
        if (ch + 1 < NCHUNK) {
            const __half* xh = xh_b + (size_t)(ch + 1) * LT * DIM;
            u32 xbuf = sb + SM_X + ((ch + 1) & 1) * ARR;
            for (int idx = tid; idx < 128 * 16; idx += THREADS) {
                int r = idx >> 4, gq = idx & 15;
                cp16(xbuf + (u32)(r * ROWB + gq * 16), xh + r * DIM + gq * 8);
            }
            CP_COMMIT();
        }

        const u32 xS = sb + SM_X + (ch & 1) * ARR;

        // ---- GEMM1: S = U . x^T ----
        float S[16][4];
        #pragma unroll
        for (int j = 0; j < 16; j++)
            #pragma unroll
            for (int q = 0; q < 4; q++) S[j][q] = 0.0f;

        #pragma unroll
        for (int kb = 0; kb < 8; kb++) {
            u32 aU[4];
            ldmx4(aU, sb + SM_U + aU_row + kb * 32);
            #pragma unroll
            for (int jn2 = 0; jn2 < 8; jn2++) {
                u32 bX[4];
                ldmx4(bX, xS + bS_base + (u32)(16 * jn2 * ROWB + kb * 32));
                mma_f16(S[2 * jn2],     aU, bX[0], bX[1]);
                mma_f16(S[2 * jn2 + 1], aU, bX[2], bX[3]);
            }
        }

        // ---- fused epilogue + GEMM2 ----
        #pragma unroll
        for (int kb = 0; kb < 8; kb++) {
            u32 Ap[4];
            #pragma unroll
            for (int jj = 0; jj < 2; jj++) {
                int j = 2 * kb + jj;
                float e[4];
                #pragma unroll
                for (int q = 0; q < 4; q++) {
                    int l = 8 * j + 2 * tig + (q & 1);
                    e[q] = (l < lvalid) ? __expf(S[j][q]) : 0.0f;
                }
                rs0 += e[0] + e[1];
                rs1 += e[2] + e[3];
                Ap[2 * jj]     = pack2h(__float2half_rn(e[0]), __float2half_rn(e[1]));
                Ap[2 * jj + 1] = pack2h(__float2half_rn(e[2]), __float2half_rn(e[3]));
            }
            #pragma unroll
            for (int jn2 = 0; jn2 < 8; jn2++) {
                u32 bX[4];
                ldmx4t(bX, xS + bO_base + (u32)(16 * kb * ROWB + 2 * jn2 * 16));
                mma_f16(O[2 * jn2],     Ap, bX[0], bX[1]);
                mma_f16(O[2 * jn2 + 1], Ap, bX[2], bX[3]);
            }
        }
    }

    // ---- reduce row sums across quad, normalize, store ----
    rs0 += __shfl_xor_sync(0xffffffffu, rs0, 1);
    rs0 += __shfl_xor_sync(0xffffffffu, rs0, 2);
    rs1 += __shfl_xor_sync(0xffffffffu, rs1, 1);
    rs1 += __shfl_xor_sync(0xffffffffu, rs1, 2);
    float inv0 = 1.0f / rs0, inv1 = 1.0f / rs1;

    int c_row0 = c0 + 16 * w + g;
    int c_row1 = c_row0 + 8;
    float* orow0 = out + ((size_t)b * NCLS + c_row0) * DIM;
    float* orow1 = out + ((size_t)b * NCLS + c_row1) * DIM;
    #pragma unroll
    for (int j = 0; j < 16; j++) {
        int d = 8 * j + 2 * tig;
        if (c_row0 < NCLS)
            *(float2*)(orow0 + d) = make_float2(O[j][0] * inv0, O[j][1] * inv0);
        if (c_row1 < NCLS)
            *(float2*)(orow1 + d) = make_float2(O[j][2] * inv1, O[j][3] * inv1);
    }
}

extern "C" void kernel_launch(void* const* d_in, const int* in_sizes, int n_in,
                              void* d_out, int out_size)
{
    const float* x = (const float*)d_in[0];   // [8, 2500, 128]
    const float* U = (const float*)d_in[1];   // [8921, 128]
    float* out = (float*)d_out;               // [8, 8921, 128]

    const int NTOT = BATCH * LPAD * DIM / 4 + CPAD * DIM / 4;
    split_kernel<<<(NTOT + 255) / 256, 256>>>(x, U);

    cudaFuncSetAttribute(lwa_mma_kernel,
                         cudaFuncAttributeMaxDynamicSharedMemorySize, SMEM_BYTES);
    dim3 grid((NCLS + CT - 1) / CT, BATCH);   // (140, 8)
    lwa_mma_kernel<<<grid, THREADS, SMEM_BYTES>>>(out);
}